// round 15
// baseline (speedup 1.0000x reference)
#include <cuda_runtime.h>
#include <cuda_fp16.h>
#include <cstdint>
#include <cstddef>

#define N_NODES 8192
#define F_DIM   128
#define KC      64
#define KSPLIT  4
#define JSPAN   (N_NODES / KSPLIT)   // 2048
#define CHUNKS  (JSPAN / KC)         // 32
#define M_CTA   128

// smem bytes: A[2][128][144B] = 36864, B[2][128][144B] = 36864, pi[128]f
#define A_OFF(b)  ((b) * 18432)
#define B_OFF(b)  (36864 + (b) * 18432)
#define PI_OFF    73728
#define DYN_SMEM  74240

// ---- scratch ----
__device__ __half g_hh  [N_NODES * F_DIM];              // h fp16 [i][f]
__device__ __half g_hT  [(size_t)F_DIM * N_NODES];      // h fp16 transposed [f][j]
__device__ float  g_q   [N_NODES];                      // exp(0.8*f1)
__device__ float4 g_jc  [N_NODES];                      // {exp(f2), exp(0.2*f2), W2, 0}
__device__ float  g_part[KSPLIT][N_NODES * F_DIM];      // partial numerators
__device__ float  g_z   [KSPLIT][N_NODES];              // partial z
__device__ float  g_rp  [KSPLIT][N_NODES];              // partial r

// ===================== helpers =====================
__device__ __forceinline__ uint32_t smem_u32(const void* p) {
    uint32_t a;
    asm("{ .reg .u64 t; cvta.to.shared.u64 t, %1; cvt.u32.u64 %0, t; }" : "=r"(a) : "l"(p));
    return a;
}
__device__ __forceinline__ void mma16(float* d, const uint32_t* a, uint32_t b0, uint32_t b1) {
    asm volatile("mma.sync.aligned.m16n8k16.row.col.f32.f16.f16.f32 "
        "{%0,%1,%2,%3}, {%4,%5,%6,%7}, {%8,%9}, {%0,%1,%2,%3};"
        : "+f"(d[0]), "+f"(d[1]), "+f"(d[2]), "+f"(d[3])
        : "r"(a[0]), "r"(a[1]), "r"(a[2]), "r"(a[3]), "r"(b0), "r"(b1));
}
__device__ __forceinline__ void ldsm4(uint32_t* r, uint32_t addr) {
    asm volatile("ldmatrix.sync.aligned.m8n8.x4.shared.b16 {%0,%1,%2,%3}, [%4];"
        : "=r"(r[0]), "=r"(r[1]), "=r"(r[2]), "=r"(r[3]) : "r"(addr));
}
__device__ __forceinline__ void cp16(uint32_t daddr, const void* gsrc) {
    asm volatile("cp.async.cg.shared.global [%0], [%1], 16;"
                 :: "r"(daddr), "l"(gsrc) : "memory");
}
__device__ __forceinline__ void l2pf(const void* p) {
    asm volatile("prefetch.global.L2 [%0];" :: "l"(p));
}

// ===================== Kernel 1: prep =====================
__global__ __launch_bounds__(256) void prep_kernel(const float* __restrict__ x,
                                                   const float* __restrict__ W,
                                                   const float* __restrict__ a,
                                                   const float* __restrict__ W2) {
    int wid = threadIdx.x >> 5, lane = threadIdx.x & 31;
    int i = blockIdx.x * 8 + wid;
    float4 xv = *(const float4*)&x[(size_t)i * F_DIM + lane * 4];
    float4 wv = *(const float4*)&W[(size_t)i * F_DIM + lane * 4];
    float4 h;
    h.x = xv.x * wv.x; h.y = xv.y * wv.y; h.z = xv.z * wv.z; h.w = xv.w * wv.w;
    __half2 p01 = __floats2half2_rn(h.x, h.y);
    __half2 p23 = __floats2half2_rn(h.z, h.w);
    uint2 pk;
    pk.x = *(uint32_t*)&p01;
    pk.y = *(uint32_t*)&p23;
    *(uint2*)&g_hh[(size_t)i * F_DIM + lane * 4] = pk;

    float4 a1 = *(const float4*)&a[lane * 4];
    float4 a2 = *(const float4*)&a[F_DIM + lane * 4];
    float p1 = h.x * a1.x + h.y * a1.y + h.z * a1.z + h.w * a1.w;
    float p2 = h.x * a2.x + h.y * a2.y + h.z * a2.z + h.w * a2.w;
    #pragma unroll
    for (int off = 16; off; off >>= 1) {
        p1 += __shfl_xor_sync(0xffffffffu, p1, off);
        p2 += __shfl_xor_sync(0xffffffffu, p2, off);
    }
    if (lane == 0) {
        g_q[i] = expf(0.8f * p1);
        float4 jc;
        jc.x = expf(p2);
        jc.y = expf(0.2f * p2);
        jc.z = W2[i];
        jc.w = 0.f;
        g_jc[i] = jc;
    }
}

// ===================== Kernel 2: transpose fp16 =====================
__global__ __launch_bounds__(256) void transpose_kernel() {
    __shared__ __half t[32][33];
    int j0 = blockIdx.x * 32, f0 = blockIdx.y * 32;
    int tx = threadIdx.x & 31, ty = threadIdx.x >> 5;
    #pragma unroll
    for (int k = 0; k < 4; k++)
        t[ty + k * 8][tx] = g_hh[(size_t)(j0 + ty + k * 8) * F_DIM + f0 + tx];
    __syncthreads();
    #pragma unroll
    for (int k = 0; k < 4; k++)
        g_hT[(size_t)(f0 + ty + k * 8) * N_NODES + j0 + tx] = t[tx][ty + k * 8];
}

// ===================== Kernel 3: split-K fp16 mma attention =====================
// grid (64, 4): x = i-block (128 rows), y = j-split (2048 cols). 256 CTAs,
// 2 CTAs/SM, one wave. 256 threads / 8 warps; warp tile 64x32.
// Build: 16 half-warp groups x 8 rows; lane(sub 0..15) owns j quad 4*sub..+3.
// adj batch-0 register-prefetched during previous mma; batch-1 L2-prefetched.
__global__ __launch_bounds__(256, 2) void attn_kernel(const int* __restrict__ adj) {
    extern __shared__ char smc[];
    uint32_t sb = smem_u32(smc);
    float* pi_s = (float*)(smc + PI_OFF);

    int tid = threadIdx.x, wid = tid >> 5, lane = tid & 31;
    int i0 = blockIdx.x * M_CTA;
    int split = blockIdx.y;
    int jbase = split * JSPAN;
    int mw = wid & 1, nw = wid >> 1;              // 2 m-bands x 4 n-bands
    int g = tid >> 4, sub = tid & 15;             // build groups

    // ldmatrix per-lane offsets (row stride 144B; conflict-free)
    uint32_t offA = (uint32_t)(lane & 15) * 144u + (uint32_t)(lane & 16);
    uint32_t offB = ((uint32_t)(lane & 7) + ((uint32_t)(lane & 16) >> 1)) * 144u
                  + ((uint32_t)(lane & 8) << 1);

    // pi cache
    if (tid < M_CTA) pi_s[tid] = g_q[i0 + tid];

    float zp[8], rp[8];
    #pragma unroll
    for (int k = 0; k < 8; k++) { zp[k] = 0.f; rp[k] = 0.f; }

    float acc[4][4][4];
    #pragma unroll
    for (int mt = 0; mt < 4; mt++)
        #pragma unroll
        for (int nt = 0; nt < 4; nt++)
            acc[mt][nt][0] = acc[mt][nt][1] = acc[mt][nt][2] = acc[mt][nt][3] = 0.f;

    const int* ap = adj + (size_t)(i0 + g * 8) * N_NODES + jbase + 4 * sub;

    // ---- prologue: B(0) in flight; adj batch-0 of chunk 0 prefetched ----
    int4 av0[4];
    #pragma unroll
    for (int k = 0; k < 4; k++)
        av0[k] = __ldcs((const int4*)(ap + (size_t)k * N_NODES));
    #pragma unroll
    for (int k = 4; k < 8; k++)
        l2pf(ap + (size_t)k * N_NODES);
    #pragma unroll
    for (int p = 0; p < 4; p++) {
        int idx = tid + p * 256;
        int col = idx >> 3, seg = idx & 7;
        cp16(sb + B_OFF(0) + col * 144 + seg * 16,
             &g_hT[(size_t)col * N_NODES + jbase + seg * 8]);
    }
    asm volatile("cp.async.commit_group;" ::: "memory");
    __syncthreads();   // pi_s visible

    for (int c = 0; c < CHUNKS; c++) {
        int bu = c & 1;
        // ---- build A tile: 8 rows per group ----
        {
            int jc_i = jbase + c * KC + 4 * sub;
            float4 jc0 = g_jc[jc_i + 0];
            float4 jc1 = g_jc[jc_i + 1];
            float4 jc2 = g_jc[jc_i + 2];
            float4 jc3 = g_jc[jc_i + 3];
            const int* apc = ap + c * KC;
            // issue batch-1 loads early (L2-hit thanks to prefetch)
            int4 av1[4];
            #pragma unroll
            for (int k = 0; k < 4; k++)
                av1[k] = __ldcs((const int4*)(apc + (size_t)(4 + k) * N_NODES));
            // batch 0 from prefetched av0
            #pragma unroll
            for (int k = 0; k < 4; k++) {
                int row = g * 8 + k;
                float piv = pi_s[row];
                float w0 = av0[k].x ? fmaxf(piv * jc0.x, jc0.y) : 0.f;
                float w1 = av0[k].y ? fmaxf(piv * jc1.x, jc1.y) : 0.f;
                float w2 = av0[k].z ? fmaxf(piv * jc2.x, jc2.y) : 0.f;
                float w3 = av0[k].w ? fmaxf(piv * jc3.x, jc3.y) : 0.f;
                __half2 h01 = __floats2half2_rn(w0, w1);
                __half2 h23 = __floats2half2_rn(w2, w3);
                uint2 pk;
                pk.x = *(uint32_t*)&h01;
                pk.y = *(uint32_t*)&h23;
                *(uint2*)(smc + A_OFF(bu) + row * 144 + sub * 8) = pk;
                zp[k] += __low2float(h01) + __high2float(h01)
                       + __low2float(h23) + __high2float(h23);
                rp[k] += (av0[k].x ? jc0.z : 0.f) + (av0[k].y ? jc1.z : 0.f)
                       + (av0[k].z ? jc2.z : 0.f) + (av0[k].w ? jc3.z : 0.f);
            }
            // batch 1
            #pragma unroll
            for (int k = 0; k < 4; k++) {
                int row = g * 8 + 4 + k;
                float piv = pi_s[row];
                float w0 = av1[k].x ? fmaxf(piv * jc0.x, jc0.y) : 0.f;
                float w1 = av1[k].y ? fmaxf(piv * jc1.x, jc1.y) : 0.f;
                float w2 = av1[k].z ? fmaxf(piv * jc2.x, jc2.y) : 0.f;
                float w3 = av1[k].w ? fmaxf(piv * jc3.x, jc3.y) : 0.f;
                __half2 h01 = __floats2half2_rn(w0, w1);
                __half2 h23 = __floats2half2_rn(w2, w3);
                uint2 pk;
                pk.x = *(uint32_t*)&h01;
                pk.y = *(uint32_t*)&h23;
                *(uint2*)(smc + A_OFF(bu) + row * 144 + sub * 8) = pk;
                zp[4 + k] += __low2float(h01) + __high2float(h01)
                           + __low2float(h23) + __high2float(h23);
                rp[4 + k] += (av1[k].x ? jc0.z : 0.f) + (av1[k].y ? jc1.z : 0.f)
                           + (av1[k].z ? jc2.z : 0.f) + (av1[k].w ? jc3.z : 0.f);
            }
        }
        asm volatile("cp.async.wait_group 0;" ::: "memory");   // B(c) landed
        __syncthreads();                                        // A(c)+B(c) visible
        // ---- issue B(c+1); prefetch adj for c+1 (overlaps mma) ----
        if (c + 1 < CHUNKS) {
            #pragma unroll
            for (int p = 0; p < 4; p++) {
                int idx = tid + p * 256;
                int col = idx >> 3, seg = idx & 7;
                cp16(sb + B_OFF(bu ^ 1) + col * 144 + seg * 16,
                     &g_hT[(size_t)col * N_NODES + jbase + (c + 1) * KC + seg * 8]);
            }
            asm volatile("cp.async.commit_group;" ::: "memory");
            const int* apn = ap + (c + 1) * KC;
            #pragma unroll
            for (int k = 0; k < 4; k++)
                av0[k] = __ldcs((const int4*)(apn + (size_t)k * N_NODES));
            #pragma unroll
            for (int k = 4; k < 8; k++)
                l2pf(apn + (size_t)k * N_NODES);
        }
        // ---- mma: 4 k16 steps, warp tile 64x32 ----
        uint32_t Ab = sb + A_OFF(bu) + (mw * 64) * 144 + offA;
        uint32_t Bb = sb + B_OFF(bu) + (nw * 32) * 144 + offB;
        #pragma unroll
        for (int s = 0; s < 4; s++) {
            uint32_t af[4][4], bq0[4], bq1[4];
            #pragma unroll
            for (int mt = 0; mt < 4; mt++)
                ldsm4(af[mt], Ab + mt * 16 * 144 + s * 32);
            ldsm4(bq0, Bb + s * 32);
            ldsm4(bq1, Bb + 16 * 144 + s * 32);
            #pragma unroll
            for (int mt = 0; mt < 4; mt++) {
                mma16(acc[mt][0], af[mt], bq0[0], bq0[1]);
                mma16(acc[mt][1], af[mt], bq0[2], bq0[3]);
                mma16(acc[mt][2], af[mt], bq1[0], bq1[1]);
                mma16(acc[mt][3], af[mt], bq1[2], bq1[3]);
            }
        }
    }

    // ---- reduce z, r across the 16-lane group (sub); write split partials ----
    #pragma unroll
    for (int k = 0; k < 8; k++) {
        float z = zp[k], r = rp[k];
        #pragma unroll
        for (int off = 8; off; off >>= 1) {
            z += __shfl_xor_sync(0xffffffffu, z, off);
            r += __shfl_xor_sync(0xffffffffu, r, off);
        }
        zp[k] = z; rp[k] = r;
    }
    if (sub == 0) {
        #pragma unroll
        for (int k = 0; k < 8; k++) {
            g_z [split][i0 + g * 8 + k] = zp[k];
            g_rp[split][i0 + g * 8 + k] = rp[k];
        }
    }

    // ---- write partial numerators ----
    int gl = lane >> 2, ql = lane & 3;
    float* part = g_part[split];
    #pragma unroll
    for (int mt = 0; mt < 4; mt++) {
        int r0 = mw * 64 + mt * 16 + gl;
        #pragma unroll
        for (int nt = 0; nt < 4; nt++) {
            int col = nw * 32 + nt * 8 + ql * 2;
            *(float2*)&part[(size_t)(i0 + r0) * F_DIM + col] =
                make_float2(acc[mt][nt][0], acc[mt][nt][1]);
            *(float2*)&part[(size_t)(i0 + r0 + 8) * F_DIM + col] =
                make_float2(acc[mt][nt][2], acc[mt][nt][3]);
        }
    }
}

// ===================== Kernel 4: combine partials =====================
__global__ __launch_bounds__(256) void combine_kernel(float* __restrict__ hp) {
    int idx = blockIdx.x * 256 + threadIdx.x;   // float4 index
    int i = idx >> 5;
    float z = g_z[0][i] + g_z[1][i] + g_z[2][i] + g_z[3][i];
    float inv = 1.0f / z;
    float4 s0 = ((const float4*)g_part[0])[idx];
    float4 s1 = ((const float4*)g_part[1])[idx];
    float4 s2 = ((const float4*)g_part[2])[idx];
    float4 s3 = ((const float4*)g_part[3])[idx];
    float4 o;
    o.x = (s0.x + s1.x + s2.x + s3.x) * inv;
    o.y = (s0.y + s1.y + s2.y + s3.y) * inv;
    o.z = (s0.z + s1.z + s2.z + s3.z) * inv;
    o.w = (s0.w + s1.w + s2.w + s3.w) * inv;
    ((float4*)hp)[idx] = o;
}

// ===================== Kernel 5: out = elu(r^T @ x) =====================
__global__ void out_kernel(const float* __restrict__ x, float* __restrict__ out) {
    int f = blockIdx.x;
    float p = 0.f;
    for (int i = threadIdx.x; i < N_NODES; i += 256) {
        float r = g_rp[0][i] + g_rp[1][i] + g_rp[2][i] + g_rp[3][i];
        p += r * x[(size_t)i * F_DIM + f];
    }
    #pragma unroll
    for (int off = 16; off; off >>= 1)
        p += __shfl_xor_sync(0xffffffffu, p, off);
    __shared__ float s[8];
    int lane = threadIdx.x & 31, wid = threadIdx.x >> 5;
    if (lane == 0) s[wid] = p;
    __syncthreads();
    if (threadIdx.x == 0) {
        float v = 0.f;
        #pragma unroll
        for (int k = 0; k < 8; k++) v += s[k];
        out[f] = (v > 0.f) ? v : (expf(v) - 1.0f);
    }
}

// ===========================================================================
extern "C" void kernel_launch(void* const* d_in, const int* in_sizes, int n_in,
                              void* d_out, int out_size) {
    const float* x   = (const float*)d_in[0];
    const int*   adj = (const int*)  d_in[1];
    const float* W   = (const float*)d_in[2];
    const float* a   = (const float*)d_in[3];
    const float* W2  = (const float*)d_in[4];
    float* out = (float*)d_out;   // [0:128) elu output, [128:) h_prime

    cudaFuncSetAttribute(attn_kernel, cudaFuncAttributeMaxDynamicSharedMemorySize, DYN_SMEM);

    prep_kernel<<<N_NODES / 8, 256>>>(x, W, a, W2);
    transpose_kernel<<<dim3(N_NODES / 32, F_DIM / 32), 256>>>();
    attn_kernel<<<dim3(N_NODES / M_CTA, KSPLIT), 256, DYN_SMEM>>>(adj);
    combine_kernel<<<(N_NODES * F_DIM / 4) / 256, 256>>>(out + F_DIM);
    out_kernel<<<F_DIM, 256>>>(x, out);
}

// round 16
// speedup vs baseline: 1.1481x; 1.1481x over previous
#include <cuda_runtime.h>
#include <cuda_fp16.h>
#include <cstdint>
#include <cstddef>

#define N_NODES 8192
#define F_DIM   128
#define KC      64
#define KSPLIT  4
#define JSPAN   (N_NODES / KSPLIT)   // 2048
#define CHUNKS  (JSPAN / KC)         // 32
#define M_CTA   128

// smem bytes: A[2][128][144B] = 36864, B[2][128][144B] = 36864, pi[128]f
#define A_OFF(b)  ((b) * 18432)
#define B_OFF(b)  (36864 + (b) * 18432)
#define PI_OFF    73728
#define DYN_SMEM  74240

// ---- scratch ----
__device__ __half g_hh  [N_NODES * F_DIM];              // h fp16 [i][f]
__device__ __half g_hT  [(size_t)F_DIM * N_NODES];      // h fp16 transposed [f][j]
__device__ float  g_q   [N_NODES];                      // exp(0.8*f1)
__device__ float4 g_jc  [N_NODES];                      // {exp(f2), exp(0.2*f2), W2, 0}
__device__ float  g_part[KSPLIT][N_NODES * F_DIM];      // partial numerators
__device__ float  g_z   [KSPLIT][N_NODES];              // partial z
__device__ float  g_rp  [KSPLIT][N_NODES];              // partial r

// ===================== helpers =====================
__device__ __forceinline__ uint32_t smem_u32(const void* p) {
    uint32_t a;
    asm("{ .reg .u64 t; cvta.to.shared.u64 t, %1; cvt.u32.u64 %0, t; }" : "=r"(a) : "l"(p));
    return a;
}
__device__ __forceinline__ void mma16(float* d, const uint32_t* a, uint32_t b0, uint32_t b1) {
    asm volatile("mma.sync.aligned.m16n8k16.row.col.f32.f16.f16.f32 "
        "{%0,%1,%2,%3}, {%4,%5,%6,%7}, {%8,%9}, {%0,%1,%2,%3};"
        : "+f"(d[0]), "+f"(d[1]), "+f"(d[2]), "+f"(d[3])
        : "r"(a[0]), "r"(a[1]), "r"(a[2]), "r"(a[3]), "r"(b0), "r"(b1));
}
__device__ __forceinline__ void ldsm4(uint32_t* r, uint32_t addr) {
    asm volatile("ldmatrix.sync.aligned.m8n8.x4.shared.b16 {%0,%1,%2,%3}, [%4];"
        : "=r"(r[0]), "=r"(r[1]), "=r"(r[2]), "=r"(r[3]) : "r"(addr));
}
__device__ __forceinline__ void cp16(uint32_t daddr, const void* gsrc) {
    asm volatile("cp.async.cg.shared.global [%0], [%1], 16;"
                 :: "r"(daddr), "l"(gsrc) : "memory");
}

// ===================== Kernel 1: prep =====================
__global__ __launch_bounds__(256) void prep_kernel(const float* __restrict__ x,
                                                   const float* __restrict__ W,
                                                   const float* __restrict__ a,
                                                   const float* __restrict__ W2) {
    int wid = threadIdx.x >> 5, lane = threadIdx.x & 31;
    int i = blockIdx.x * 8 + wid;
    float4 xv = *(const float4*)&x[(size_t)i * F_DIM + lane * 4];
    float4 wv = *(const float4*)&W[(size_t)i * F_DIM + lane * 4];
    float4 h;
    h.x = xv.x * wv.x; h.y = xv.y * wv.y; h.z = xv.z * wv.z; h.w = xv.w * wv.w;
    __half2 p01 = __floats2half2_rn(h.x, h.y);
    __half2 p23 = __floats2half2_rn(h.z, h.w);
    uint2 pk;
    pk.x = *(uint32_t*)&p01;
    pk.y = *(uint32_t*)&p23;
    *(uint2*)&g_hh[(size_t)i * F_DIM + lane * 4] = pk;

    float4 a1 = *(const float4*)&a[lane * 4];
    float4 a2 = *(const float4*)&a[F_DIM + lane * 4];
    float p1 = h.x * a1.x + h.y * a1.y + h.z * a1.z + h.w * a1.w;
    float p2 = h.x * a2.x + h.y * a2.y + h.z * a2.z + h.w * a2.w;
    #pragma unroll
    for (int off = 16; off; off >>= 1) {
        p1 += __shfl_xor_sync(0xffffffffu, p1, off);
        p2 += __shfl_xor_sync(0xffffffffu, p2, off);
    }
    if (lane == 0) {
        g_q[i] = expf(0.8f * p1);
        float4 jc;
        jc.x = expf(p2);
        jc.y = expf(0.2f * p2);
        jc.z = W2[i];
        jc.w = 0.f;
        g_jc[i] = jc;
    }
}

// ===================== Kernel 2: transpose fp16 =====================
__global__ __launch_bounds__(256) void transpose_kernel() {
    __shared__ __half t[32][33];
    int j0 = blockIdx.x * 32, f0 = blockIdx.y * 32;
    int tx = threadIdx.x & 31, ty = threadIdx.x >> 5;
    #pragma unroll
    for (int k = 0; k < 4; k++)
        t[ty + k * 8][tx] = g_hh[(size_t)(j0 + ty + k * 8) * F_DIM + f0 + tx];
    __syncthreads();
    #pragma unroll
    for (int k = 0; k < 4; k++)
        g_hT[(size_t)(f0 + ty + k * 8) * N_NODES + j0 + tx] = t[tx][ty + k * 8];
}

// ===================== Kernel 3: split-K fp16 mma attention =====================
// grid (64, 4): x = i-block (128 rows), y = j-split (2048 cols). 256 CTAs,
// 2 CTAs/SM, one wave. 256 threads / 8 warps; warp tile 64x32.
// Build: 16 half-warp groups x 8 rows; lane(sub 0..15) owns j quad 4*sub..+3.
__global__ __launch_bounds__(256, 2) void attn_kernel(const int* __restrict__ adj) {
    extern __shared__ char smc[];
    uint32_t sb = smem_u32(smc);
    float* pi_s = (float*)(smc + PI_OFF);

    int tid = threadIdx.x, wid = tid >> 5, lane = tid & 31;
    int i0 = blockIdx.x * M_CTA;
    int split = blockIdx.y;
    int jbase = split * JSPAN;
    int mw = wid & 1, nw = wid >> 1;              // 2 m-bands x 4 n-bands
    int g = tid >> 4, sub = tid & 15;             // build groups

    // ldmatrix per-lane offsets (row stride 144B; conflict-free)
    uint32_t offA = (uint32_t)(lane & 15) * 144u + (uint32_t)(lane & 16);
    uint32_t offB = ((uint32_t)(lane & 7) + ((uint32_t)(lane & 16) >> 1)) * 144u
                  + ((uint32_t)(lane & 8) << 1);

    // pi cache
    if (tid < M_CTA) pi_s[tid] = g_q[i0 + tid];

    float zp[8], rp[8];
    #pragma unroll
    for (int k = 0; k < 8; k++) { zp[k] = 0.f; rp[k] = 0.f; }

    float acc[4][4][4];
    #pragma unroll
    for (int mt = 0; mt < 4; mt++)
        #pragma unroll
        for (int nt = 0; nt < 4; nt++)
            acc[mt][nt][0] = acc[mt][nt][1] = acc[mt][nt][2] = acc[mt][nt][3] = 0.f;

    const int* ap = adj + (size_t)(i0 + g * 8) * N_NODES + jbase + 4 * sub;

    // ---- prologue: B(0) in flight ----
    #pragma unroll
    for (int p = 0; p < 4; p++) {
        int idx = tid + p * 256;
        int col = idx >> 3, seg = idx & 7;
        cp16(sb + B_OFF(0) + col * 144 + seg * 16,
             &g_hT[(size_t)col * N_NODES + jbase + seg * 8]);
    }
    asm volatile("cp.async.commit_group;" ::: "memory");
    __syncthreads();   // pi_s visible

    for (int c = 0; c < CHUNKS; c++) {
        int bu = c & 1;
        // ---- build A tile: 8 rows per group, 2 batches of 4 rows ----
        {
            int jc_i = jbase + c * KC + 4 * sub;
            float4 jc0 = g_jc[jc_i + 0];
            float4 jc1 = g_jc[jc_i + 1];
            float4 jc2 = g_jc[jc_i + 2];
            float4 jc3 = g_jc[jc_i + 3];
            const int* apc = ap + c * KC;
            #pragma unroll
            for (int b2 = 0; b2 < 2; b2++) {
                int4 av[4];
                #pragma unroll
                for (int k = 0; k < 4; k++)
                    av[k] = __ldcs((const int4*)(apc + (size_t)(b2 * 4 + k) * N_NODES));
                #pragma unroll
                for (int k = 0; k < 4; k++) {
                    int row = g * 8 + b2 * 4 + k;
                    float piv = pi_s[row];
                    float w0 = av[k].x ? fmaxf(piv * jc0.x, jc0.y) : 0.f;
                    float w1 = av[k].y ? fmaxf(piv * jc1.x, jc1.y) : 0.f;
                    float w2 = av[k].z ? fmaxf(piv * jc2.x, jc2.y) : 0.f;
                    float w3 = av[k].w ? fmaxf(piv * jc3.x, jc3.y) : 0.f;
                    __half2 h01 = __floats2half2_rn(w0, w1);
                    __half2 h23 = __floats2half2_rn(w2, w3);
                    uint2 pk;
                    pk.x = *(uint32_t*)&h01;
                    pk.y = *(uint32_t*)&h23;
                    *(uint2*)(smc + A_OFF(bu) + row * 144 + sub * 8) = pk;
                    zp[b2 * 4 + k] += __low2float(h01) + __high2float(h01)
                                    + __low2float(h23) + __high2float(h23);
                    rp[b2 * 4 + k] += (av[k].x ? jc0.z : 0.f) + (av[k].y ? jc1.z : 0.f)
                                    + (av[k].z ? jc2.z : 0.f) + (av[k].w ? jc3.z : 0.f);
                }
            }
        }
        asm volatile("cp.async.wait_group 0;" ::: "memory");   // B(c) landed
        __syncthreads();                                        // A(c)+B(c) visible
        // ---- issue B(c+1) (overlaps mma) ----
        if (c + 1 < CHUNKS) {
            #pragma unroll
            for (int p = 0; p < 4; p++) {
                int idx = tid + p * 256;
                int col = idx >> 3, seg = idx & 7;
                cp16(sb + B_OFF(bu ^ 1) + col * 144 + seg * 16,
                     &g_hT[(size_t)col * N_NODES + jbase + (c + 1) * KC + seg * 8]);
            }
            asm volatile("cp.async.commit_group;" ::: "memory");
        }
        // ---- mma: 4 k16 steps, warp tile 64x32 ----
        uint32_t Ab = sb + A_OFF(bu) + (mw * 64) * 144 + offA;
        uint32_t Bb = sb + B_OFF(bu) + (nw * 32) * 144 + offB;
        #pragma unroll
        for (int s = 0; s < 4; s++) {
            uint32_t af[4][4], bq0[4], bq1[4];
            #pragma unroll
            for (int mt = 0; mt < 4; mt++)
                ldsm4(af[mt], Ab + mt * 16 * 144 + s * 32);
            ldsm4(bq0, Bb + s * 32);
            ldsm4(bq1, Bb + 16 * 144 + s * 32);
            #pragma unroll
            for (int mt = 0; mt < 4; mt++) {
                mma16(acc[mt][0], af[mt], bq0[0], bq0[1]);
                mma16(acc[mt][1], af[mt], bq0[2], bq0[3]);
                mma16(acc[mt][2], af[mt], bq1[0], bq1[1]);
                mma16(acc[mt][3], af[mt], bq1[2], bq1[3]);
            }
        }
    }

    // ---- reduce z, r across the 16-lane group (sub); write split partials ----
    #pragma unroll
    for (int k = 0; k < 8; k++) {
        float z = zp[k], r = rp[k];
        #pragma unroll
        for (int off = 8; off; off >>= 1) {
            z += __shfl_xor_sync(0xffffffffu, z, off);
            r += __shfl_xor_sync(0xffffffffu, r, off);
        }
        zp[k] = z; rp[k] = r;
    }
    if (sub == 0) {
        #pragma unroll
        for (int k = 0; k < 8; k++) {
            g_z [split][i0 + g * 8 + k] = zp[k];
            g_rp[split][i0 + g * 8 + k] = rp[k];
        }
    }

    // ---- write partial numerators ----
    int gl = lane >> 2, ql = lane & 3;
    float* part = g_part[split];
    #pragma unroll
    for (int mt = 0; mt < 4; mt++) {
        int r0 = mw * 64 + mt * 16 + gl;
        #pragma unroll
        for (int nt = 0; nt < 4; nt++) {
            int col = nw * 32 + nt * 8 + ql * 2;
            *(float2*)&part[(size_t)(i0 + r0) * F_DIM + col] =
                make_float2(acc[mt][nt][0], acc[mt][nt][1]);
            *(float2*)&part[(size_t)(i0 + r0 + 8) * F_DIM + col] =
                make_float2(acc[mt][nt][2], acc[mt][nt][3]);
        }
    }
}

// ===================== Kernel 4: combine partials (2x ILP) =====================
__global__ __launch_bounds__(256) void combine_kernel(float* __restrict__ hp) {
    int base = (blockIdx.x * 256 + threadIdx.x) * 2;   // 2 consecutive float4
    int i = base >> 5;                                  // 32 float4 per row
    float z = g_z[0][i] + g_z[1][i] + g_z[2][i] + g_z[3][i];
    float inv = 1.0f / z;
    #pragma unroll
    for (int t = 0; t < 2; t++) {
        int idx = base + t;
        float4 s0 = ((const float4*)g_part[0])[idx];
        float4 s1 = ((const float4*)g_part[1])[idx];
        float4 s2 = ((const float4*)g_part[2])[idx];
        float4 s3 = ((const float4*)g_part[3])[idx];
        float4 o;
        o.x = (s0.x + s1.x + s2.x + s3.x) * inv;
        o.y = (s0.y + s1.y + s2.y + s3.y) * inv;
        o.z = (s0.z + s1.z + s2.z + s3.z) * inv;
        o.w = (s0.w + s1.w + s2.w + s3.w) * inv;
        ((float4*)hp)[idx] = o;
    }
}

// ===================== Kernel 5: out = elu(r^T @ x) =====================
__global__ void out_kernel(const float* __restrict__ x, float* __restrict__ out) {
    int f = blockIdx.x;
    float p = 0.f;
    for (int i = threadIdx.x; i < N_NODES; i += 256) {
        float r = g_rp[0][i] + g_rp[1][i] + g_rp[2][i] + g_rp[3][i];
        p += r * x[(size_t)i * F_DIM + f];
    }
    #pragma unroll
    for (int off = 16; off; off >>= 1)
        p += __shfl_xor_sync(0xffffffffu, p, off);
    __shared__ float s[8];
    int lane = threadIdx.x & 31, wid = threadIdx.x >> 5;
    if (lane == 0) s[wid] = p;
    __syncthreads();
    if (threadIdx.x == 0) {
        float v = 0.f;
        #pragma unroll
        for (int k = 0; k < 8; k++) v += s[k];
        out[f] = (v > 0.f) ? v : (expf(v) - 1.0f);
    }
}

// ===========================================================================
extern "C" void kernel_launch(void* const* d_in, const int* in_sizes, int n_in,
                              void* d_out, int out_size) {
    const float* x   = (const float*)d_in[0];
    const int*   adj = (const int*)  d_in[1];
    const float* W   = (const float*)d_in[2];
    const float* a   = (const float*)d_in[3];
    const float* W2  = (const float*)d_in[4];
    float* out = (float*)d_out;   // [0:128) elu output, [128:) h_prime

    cudaFuncSetAttribute(attn_kernel, cudaFuncAttributeMaxDynamicSharedMemorySize, DYN_SMEM);

    prep_kernel<<<N_NODES / 8, 256>>>(x, W, a, W2);
    transpose_kernel<<<dim3(N_NODES / 32, F_DIM / 32), 256>>>();
    attn_kernel<<<dim3(N_NODES / M_CTA, KSPLIT), 256, DYN_SMEM>>>(adj);
    combine_kernel<<<(N_NODES * F_DIM / 8) / 256, 256>>>(out + F_DIM);
    out_kernel<<<F_DIM, 256>>>(x, out);
}

// round 17
// speedup vs baseline: 1.2882x; 1.1220x over previous
#include <cuda_runtime.h>
#include <cuda_fp16.h>
#include <cstdint>
#include <cstddef>

#define N_NODES 8192
#define F_DIM   128
#define KC      64
#define KSPLIT  4
#define JSPAN   (N_NODES / KSPLIT)   // 2048
#define CHUNKS  (JSPAN / KC)         // 32
#define M_CTA   128

// smem bytes: A[2][128][144B]=36864, B[2][128][144B]=36864,
// adjS[128][256B]=32768 (single buffer), jcS[64][16B]=1024, pi[128]f=512
#define A_OFF(b)  ((b) * 18432)
#define B_OFF(b)  (36864 + (b) * 18432)
#define ADJ_OFF   73728
#define JC_OFF    106496
#define PI_OFF    107520
#define DYN_SMEM  108032

// ---- scratch ----
__device__ __half g_hh  [N_NODES * F_DIM];              // h fp16 [i][f]
__device__ __half g_hT  [(size_t)F_DIM * N_NODES];      // h fp16 transposed [f][j]
__device__ float  g_q   [N_NODES];                      // exp(0.8*f1)
__device__ float4 g_jc  [N_NODES];                      // {exp(f2), exp(0.2*f2), W2, 0}
__device__ float  g_part[KSPLIT][N_NODES * F_DIM];      // partial numerators
__device__ float  g_z   [KSPLIT][N_NODES];              // partial z
__device__ float  g_rp  [KSPLIT][N_NODES];              // partial r

// ===================== helpers =====================
__device__ __forceinline__ uint32_t smem_u32(const void* p) {
    uint32_t a;
    asm("{ .reg .u64 t; cvta.to.shared.u64 t, %1; cvt.u32.u64 %0, t; }" : "=r"(a) : "l"(p));
    return a;
}
__device__ __forceinline__ void mma16(float* d, const uint32_t* a, uint32_t b0, uint32_t b1) {
    asm volatile("mma.sync.aligned.m16n8k16.row.col.f32.f16.f16.f32 "
        "{%0,%1,%2,%3}, {%4,%5,%6,%7}, {%8,%9}, {%0,%1,%2,%3};"
        : "+f"(d[0]), "+f"(d[1]), "+f"(d[2]), "+f"(d[3])
        : "r"(a[0]), "r"(a[1]), "r"(a[2]), "r"(a[3]), "r"(b0), "r"(b1));
}
__device__ __forceinline__ void ldsm4(uint32_t* r, uint32_t addr) {
    asm volatile("ldmatrix.sync.aligned.m8n8.x4.shared.b16 {%0,%1,%2,%3}, [%4];"
        : "=r"(r[0]), "=r"(r[1]), "=r"(r[2]), "=r"(r[3]) : "r"(addr));
}
__device__ __forceinline__ void cp16(uint32_t daddr, const void* gsrc) {
    asm volatile("cp.async.cg.shared.global [%0], [%1], 16;"
                 :: "r"(daddr), "l"(gsrc) : "memory");
}

// ===================== Kernel 1: prep =====================
__global__ __launch_bounds__(256) void prep_kernel(const float* __restrict__ x,
                                                   const float* __restrict__ W,
                                                   const float* __restrict__ a,
                                                   const float* __restrict__ W2) {
    int wid = threadIdx.x >> 5, lane = threadIdx.x & 31;
    int i = blockIdx.x * 8 + wid;
    float4 xv = *(const float4*)&x[(size_t)i * F_DIM + lane * 4];
    float4 wv = *(const float4*)&W[(size_t)i * F_DIM + lane * 4];
    float4 h;
    h.x = xv.x * wv.x; h.y = xv.y * wv.y; h.z = xv.z * wv.z; h.w = xv.w * wv.w;
    __half2 p01 = __floats2half2_rn(h.x, h.y);
    __half2 p23 = __floats2half2_rn(h.z, h.w);
    uint2 pk;
    pk.x = *(uint32_t*)&p01;
    pk.y = *(uint32_t*)&p23;
    *(uint2*)&g_hh[(size_t)i * F_DIM + lane * 4] = pk;

    float4 a1 = *(const float4*)&a[lane * 4];
    float4 a2 = *(const float4*)&a[F_DIM + lane * 4];
    float p1 = h.x * a1.x + h.y * a1.y + h.z * a1.z + h.w * a1.w;
    float p2 = h.x * a2.x + h.y * a2.y + h.z * a2.z + h.w * a2.w;
    #pragma unroll
    for (int off = 16; off; off >>= 1) {
        p1 += __shfl_xor_sync(0xffffffffu, p1, off);
        p2 += __shfl_xor_sync(0xffffffffu, p2, off);
    }
    if (lane == 0) {
        g_q[i] = expf(0.8f * p1);
        float4 jc;
        jc.x = expf(p2);
        jc.y = expf(0.2f * p2);
        jc.z = W2[i];
        jc.w = 0.f;
        g_jc[i] = jc;
    }
}

// ===================== Kernel 2: transpose fp16 =====================
__global__ __launch_bounds__(256) void transpose_kernel() {
    __shared__ __half t[32][33];
    int j0 = blockIdx.x * 32, f0 = blockIdx.y * 32;
    int tx = threadIdx.x & 31, ty = threadIdx.x >> 5;
    #pragma unroll
    for (int k = 0; k < 4; k++)
        t[ty + k * 8][tx] = g_hh[(size_t)(j0 + ty + k * 8) * F_DIM + f0 + tx];
    __syncthreads();
    #pragma unroll
    for (int k = 0; k < 4; k++)
        g_hT[(size_t)(f0 + ty + k * 8) * N_NODES + j0 + tx] = t[tx][ty + k * 8];
}

// ===================== Kernel 3: split-K fp16 mma attention =====================
// grid (64, 4). 256 CTAs, 2 CTAs/SM, one wave. 8 warps; warp tile 64x32.
// adj + jc + B for chunk c+1 staged via cp.async during mma(c).
__global__ __launch_bounds__(256, 2) void attn_kernel(const int* __restrict__ adj) {
    extern __shared__ char smc[];
    uint32_t sb = smem_u32(smc);
    float* pi_s = (float*)(smc + PI_OFF);

    int tid = threadIdx.x, wid = tid >> 5, lane = tid & 31;
    int i0 = blockIdx.x * M_CTA;
    int split = blockIdx.y;
    int jbase = split * JSPAN;
    int mw = wid & 1, nw = wid >> 1;              // 2 m-bands x 4 n-bands
    int g = tid >> 4, sub = tid & 15;             // build groups

    // ldmatrix per-lane offsets (row stride 144B; conflict-free)
    uint32_t offA = (uint32_t)(lane & 15) * 144u + (uint32_t)(lane & 16);
    uint32_t offB = ((uint32_t)(lane & 7) + ((uint32_t)(lane & 16) >> 1)) * 144u
                  + ((uint32_t)(lane & 8) << 1);

    if (tid < M_CTA) pi_s[tid] = g_q[i0 + tid];

    float zp[8], rp[8];
    #pragma unroll
    for (int k = 0; k < 8; k++) { zp[k] = 0.f; rp[k] = 0.f; }

    float acc[4][4][4];
    #pragma unroll
    for (int mt = 0; mt < 4; mt++)
        #pragma unroll
        for (int nt = 0; nt < 4; nt++)
            acc[mt][nt][0] = acc[mt][nt][1] = acc[mt][nt][2] = acc[mt][nt][3] = 0.f;

    // ---- prologue: stage B(0), adj(0), jc(0) ----
    {
        #pragma unroll
        for (int p = 0; p < 4; p++) {
            int idx = tid + p * 256;
            int col = idx >> 3, seg = idx & 7;
            cp16(sb + B_OFF(0) + col * 144 + seg * 16,
                 &g_hT[(size_t)col * N_NODES + jbase + seg * 8]);
        }
        #pragma unroll
        for (int p = 0; p < 8; p++) {
            int idx = tid + p * 256;
            int row = idx >> 4, seg = idx & 15;
            cp16(sb + ADJ_OFF + row * 256 + seg * 16,
                 adj + (size_t)(i0 + row) * N_NODES + jbase + seg * 4);
        }
        if (tid < 64)
            cp16(sb + JC_OFF + tid * 16, &g_jc[jbase + tid]);
        asm volatile("cp.async.commit_group;" ::: "memory");
    }

    for (int c = 0; c < CHUNKS; c++) {
        int bu = c & 1;
        asm volatile("cp.async.wait_group 0;" ::: "memory");   // B(c)+adj(c)+jc(c) landed
        __syncthreads();                                        // cross-thread visibility
        // ---- build A tile from smem-staged adj/jc ----
        {
            float4 jc0 = *(const float4*)(smc + JC_OFF + (4 * sub + 0) * 16);
            float4 jc1 = *(const float4*)(smc + JC_OFF + (4 * sub + 1) * 16);
            float4 jc2 = *(const float4*)(smc + JC_OFF + (4 * sub + 2) * 16);
            float4 jc3 = *(const float4*)(smc + JC_OFF + (4 * sub + 3) * 16);
            #pragma unroll
            for (int b2 = 0; b2 < 2; b2++) {
                int4 av[4];
                #pragma unroll
                for (int k = 0; k < 4; k++)
                    av[k] = *(const int4*)(smc + ADJ_OFF + (g * 8 + b2 * 4 + k) * 256 + sub * 16);
                #pragma unroll
                for (int k = 0; k < 4; k++) {
                    int row = g * 8 + b2 * 4 + k;
                    float piv = pi_s[row];
                    float w0 = av[k].x ? fmaxf(piv * jc0.x, jc0.y) : 0.f;
                    float w1 = av[k].y ? fmaxf(piv * jc1.x, jc1.y) : 0.f;
                    float w2 = av[k].z ? fmaxf(piv * jc2.x, jc2.y) : 0.f;
                    float w3 = av[k].w ? fmaxf(piv * jc3.x, jc3.y) : 0.f;
                    __half2 h01 = __floats2half2_rn(w0, w1);
                    __half2 h23 = __floats2half2_rn(w2, w3);
                    uint2 pk;
                    pk.x = *(uint32_t*)&h01;
                    pk.y = *(uint32_t*)&h23;
                    *(uint2*)(smc + A_OFF(bu) + row * 144 + sub * 8) = pk;
                    zp[b2 * 4 + k] += __low2float(h01) + __high2float(h01)
                                    + __low2float(h23) + __high2float(h23);
                    rp[b2 * 4 + k] += (av[k].x ? jc0.z : 0.f) + (av[k].y ? jc1.z : 0.f)
                                    + (av[k].z ? jc2.z : 0.f) + (av[k].w ? jc3.z : 0.f);
                }
            }
        }
        __syncthreads();   // A(c) visible; adjS/jcS free for restage
        // ---- stage B(c+1), adj(c+1), jc(c+1) (overlaps mma) ----
        if (c + 1 < CHUNKS) {
            int jn = jbase + (c + 1) * KC;
            #pragma unroll
            for (int p = 0; p < 4; p++) {
                int idx = tid + p * 256;
                int col = idx >> 3, seg = idx & 7;
                cp16(sb + B_OFF(bu ^ 1) + col * 144 + seg * 16,
                     &g_hT[(size_t)col * N_NODES + jn + seg * 8]);
            }
            #pragma unroll
            for (int p = 0; p < 8; p++) {
                int idx = tid + p * 256;
                int row = idx >> 4, seg = idx & 15;
                cp16(sb + ADJ_OFF + row * 256 + seg * 16,
                     adj + (size_t)(i0 + row) * N_NODES + jn + seg * 4);
            }
            if (tid < 64)
                cp16(sb + JC_OFF + tid * 16, &g_jc[jn + tid]);
            asm volatile("cp.async.commit_group;" ::: "memory");
        }
        // ---- mma: 4 k16 steps, warp tile 64x32 ----
        uint32_t Ab = sb + A_OFF(bu) + (mw * 64) * 144 + offA;
        uint32_t Bb = sb + B_OFF(bu) + (nw * 32) * 144 + offB;
        #pragma unroll
        for (int s = 0; s < 4; s++) {
            uint32_t af[4][4], bq0[4], bq1[4];
            #pragma unroll
            for (int mt = 0; mt < 4; mt++)
                ldsm4(af[mt], Ab + mt * 16 * 144 + s * 32);
            ldsm4(bq0, Bb + s * 32);
            ldsm4(bq1, Bb + 16 * 144 + s * 32);
            #pragma unroll
            for (int mt = 0; mt < 4; mt++) {
                mma16(acc[mt][0], af[mt], bq0[0], bq0[1]);
                mma16(acc[mt][1], af[mt], bq0[2], bq0[3]);
                mma16(acc[mt][2], af[mt], bq1[0], bq1[1]);
                mma16(acc[mt][3], af[mt], bq1[2], bq1[3]);
            }
        }
    }

    // ---- reduce z, r across the 16-lane group (sub); write split partials ----
    #pragma unroll
    for (int k = 0; k < 8; k++) {
        float z = zp[k], r = rp[k];
        #pragma unroll
        for (int off = 8; off; off >>= 1) {
            z += __shfl_xor_sync(0xffffffffu, z, off);
            r += __shfl_xor_sync(0xffffffffu, r, off);
        }
        zp[k] = z; rp[k] = r;
    }
    if (sub == 0) {
        #pragma unroll
        for (int k = 0; k < 8; k++) {
            g_z [split][i0 + g * 8 + k] = zp[k];
            g_rp[split][i0 + g * 8 + k] = rp[k];
        }
    }

    // ---- write partial numerators ----
    int gl = lane >> 2, ql = lane & 3;
    float* part = g_part[split];
    #pragma unroll
    for (int mt = 0; mt < 4; mt++) {
        int r0 = mw * 64 + mt * 16 + gl;
        #pragma unroll
        for (int nt = 0; nt < 4; nt++) {
            int col = nw * 32 + nt * 8 + ql * 2;
            *(float2*)&part[(size_t)(i0 + r0) * F_DIM + col] =
                make_float2(acc[mt][nt][0], acc[mt][nt][1]);
            *(float2*)&part[(size_t)(i0 + r0 + 8) * F_DIM + col] =
                make_float2(acc[mt][nt][2], acc[mt][nt][3]);
        }
    }
}

// ===================== Kernel 4: combine partials =====================
__global__ __launch_bounds__(256) void combine_kernel(float* __restrict__ hp) {
    int idx = blockIdx.x * 256 + threadIdx.x;   // float4 index
    int i = idx >> 5;
    float z = g_z[0][i] + g_z[1][i] + g_z[2][i] + g_z[3][i];
    float inv = 1.0f / z;
    float4 s0 = ((const float4*)g_part[0])[idx];
    float4 s1 = ((const float4*)g_part[1])[idx];
    float4 s2 = ((const float4*)g_part[2])[idx];
    float4 s3 = ((const float4*)g_part[3])[idx];
    float4 o;
    o.x = (s0.x + s1.x + s2.x + s3.x) * inv;
    o.y = (s0.y + s1.y + s2.y + s3.y) * inv;
    o.z = (s0.z + s1.z + s2.z + s3.z) * inv;
    o.w = (s0.w + s1.w + s2.w + s3.w) * inv;
    ((float4*)hp)[idx] = o;
}

// ===================== Kernel 5: out = elu(r^T @ x) =====================
__global__ void out_kernel(const float* __restrict__ x, float* __restrict__ out) {
    int f = blockIdx.x;
    float p = 0.f;
    for (int i = threadIdx.x; i < N_NODES; i += 256) {
        float r = g_rp[0][i] + g_rp[1][i] + g_rp[2][i] + g_rp[3][i];
        p += r * x[(size_t)i * F_DIM + f];
    }
    #pragma unroll
    for (int off = 16; off; off >>= 1)
        p += __shfl_xor_sync(0xffffffffu, p, off);
    __shared__ float s[8];
    int lane = threadIdx.x & 31, wid = threadIdx.x >> 5;
    if (lane == 0) s[wid] = p;
    __syncthreads();
    if (threadIdx.x == 0) {
        float v = 0.f;
        #pragma unroll
        for (int k = 0; k < 8; k++) v += s[k];
        out[f] = (v > 0.f) ? v : (expf(v) - 1.0f);
    }
}

// ===========================================================================
extern "C" void kernel_launch(void* const* d_in, const int* in_sizes, int n_in,
                              void* d_out, int out_size) {
    const float* x   = (const float*)d_in[0];
    const int*   adj = (const int*)  d_in[1];
    const float* W   = (const float*)d_in[2];
    const float* a   = (const float*)d_in[3];
    const float* W2  = (const float*)d_in[4];
    float* out = (float*)d_out;   // [0:128) elu output, [128:) h_prime

    cudaFuncSetAttribute(attn_kernel, cudaFuncAttributeMaxDynamicSharedMemorySize, DYN_SMEM);

    prep_kernel<<<N_NODES / 8, 256>>>(x, W, a, W2);
    transpose_kernel<<<dim3(N_NODES / 32, F_DIM / 32), 256>>>();
    attn_kernel<<<dim3(N_NODES / M_CTA, KSPLIT), 256, DYN_SMEM>>>(adj);
    combine_kernel<<<(N_NODES * F_DIM / 4) / 256, 256>>>(out + F_DIM);
    out_kernel<<<F_DIM, 256>>>(x, out);
}